// round 8
// baseline (speedup 1.0000x reference)
#include <cuda_runtime.h>

// RGBuvHistBlock: x [8,3,256,256] f32 in [0,1]; bin_vals [64] = linspace(-1,1).
// hist[nc][b] = sum_p exp(-((2x-1)-b)^2/(2*0.02^2)), normalized per nc.
//
// R8: smem-issue-bound optimization. LDS/STS cost 4 issue cyc/op regardless of
// width, so: (a) 12-bin quad-aligned window -> 3 LDS.128 + 3 STS.128 per pixel
// (guaranteed +-3.5 bin coverage); (b) float4 block reduce (16 LDS.128/thread);
// (c) SPLITS=16 to minimize per-block overhead. Weights via 3 EX2 + power chain:
// w_j = A * B^{11-2j} * K_{|5.5-j|},  A=2^{-c^2}, B=2^{-c*DS}, c = DS*(u-4q-5.5).

#define NC_TOTAL   24
#define PIX_PER_NC 65536
#define HB         64
#define SPLITS     16
#define CHUNK      4096
#define NT         128
#define NQUAD      16            // 64 bins as 16 float4 quads

#define DS_   1.3481298394f      // scaled bin spacing = sqrt(1250*log2e)*2/63
#define KC_   7.41471412f        // 5.5*DS
// K_m = 2^{-(m*DS)^2}, m = 0.5,1.5,...,5.5
#define K05  0.7298330f
#define K15  0.0587498f
#define K25  3.806934e-4f
#define K35  1.985730e-7f
#define K45  8.337990e-12f
#define K55  2.818250e-17f

__device__ float    g_part[NC_TOTAL * SPLITS * HB];
__device__ unsigned g_cnt[NC_TOTAL];

__device__ __forceinline__ float ex2f(float a) {
    float r;
    asm("ex2.approx.ftz.f32 %0, %1;" : "=f"(r) : "f"(a));
    return r;
}

__global__ __launch_bounds__(NT) void hist_fused_kernel(
    const float* __restrict__ x, const float* __restrict__ bin_vals,
    float* __restrict__ out)
{
    const int nc    = blockIdx.y;
    const int split = blockIdx.x;
    const int tid   = threadIdx.x;

    __shared__ float4 hist4[NQUAD * NT];   // 32KB: quad Q, thread t -> hist4[Q*NT+t]
    __shared__ float4 racc4[NT];           // 2KB reduce staging
    __shared__ float  ws[2];
    __shared__ int    slast;

    // Zero (16 STS.128 per thread).
#pragma unroll
    for (int i = 0; i < NQUAD; ++i)
        hist4[tid + i * NT] = make_float4(0.f, 0.f, 0.f, 0.f);
    __syncthreads();

    const float4* xp = reinterpret_cast<const float4*>(
        x + (size_t)nc * PIX_PER_NC + (size_t)split * CHUNK);

#pragma unroll 2
    for (int it = 0; it < CHUNK / (4 * NT); ++it) {
        float4 v = xp[tid + it * NT];
        float pv[4] = {v.x, v.y, v.z, v.w};
#pragma unroll
        for (int p = 0; p < 4; ++p) {
            float u  = pv[p] * 63.0f;                       // bin-unit position
            int   q  = __float2int_rn(fmaf(u, 0.25f, -1.375f));
            q = min(max(q, 0), 13);
            float c  = fmaf(u - (float)(4 * q), DS_, -KC_); // scaled offset from center

            float A  = ex2f(-c * c);
            float B  = ex2f(-c * DS_);
            float Bp = ex2f(c * DS_);

            float B2 = B * B,  P2 = Bp * Bp;
            float B3 = B2 * B, P3 = P2 * Bp;
            float B5 = B3 * B2, P5 = P3 * P2;
            float B7 = B5 * B2, P7 = P5 * P2;
            float B9 = B7 * B2, P9 = P7 * P2;
            float B11 = B9 * B2, P11 = P9 * P2;

            float t0  = B11 * K55, t1  = B9 * K45, t2  = B7 * K35;
            float t3  = B5  * K25, t4  = B3 * K15, t5  = B  * K05;
            float t6  = Bp  * K05, t7  = P3 * K15, t8  = P5 * K25;
            float t9  = P7  * K35, t10 = P9 * K45, t11 = P11 * K55;

            float4* hp = hist4 + q * NT + tid;
            float4 h0 = hp[0 * NT];
            float4 h1 = hp[1 * NT];
            float4 h2 = hp[2 * NT];
            h0.x = fmaf(A, t0,  h0.x); h0.y = fmaf(A, t1,  h0.y);
            h0.z = fmaf(A, t2,  h0.z); h0.w = fmaf(A, t3,  h0.w);
            h1.x = fmaf(A, t4,  h1.x); h1.y = fmaf(A, t5,  h1.y);
            h1.z = fmaf(A, t6,  h1.z); h1.w = fmaf(A, t7,  h1.w);
            h2.x = fmaf(A, t8,  h2.x); h2.y = fmaf(A, t9,  h2.y);
            h2.z = fmaf(A, t10, h2.z); h2.w = fmaf(A, t11, h2.w);
            hp[0 * NT] = h0;
            hp[1 * NT] = h1;
            hp[2 * NT] = h2;
        }
    }
    __syncthreads();

    // Reduce phase 1: thread (Q=tid>>3, k=tid&7) sums 16 cells of quad Q (float4).
    {
        const int Q = tid >> 3, k = tid & 7;
        const float4* hq = hist4 + Q * NT + k * 16;
        float4 acc = make_float4(0.f, 0.f, 0.f, 0.f);
#pragma unroll
        for (int i = 0; i < 16; ++i) {
            float4 hv = hq[i];
            acc.x += hv.x; acc.y += hv.y; acc.z += hv.z; acc.w += hv.w;
        }
        racc4[tid] = acc;
    }
    __syncthreads();

    // Reduce phase 2: bin b (tid<64) sums its component over 8 partials.
    if (tid < HB) {
        const int Q = tid >> 2, comp = tid & 3;
        const float* rf = reinterpret_cast<const float*>(racc4);
        float s = 0.0f;
#pragma unroll
        for (int k = 0; k < 8; ++k)
            s += rf[(Q * 8 + k) * 4 + comp];
        g_part[((size_t)nc * SPLITS + split) * HB + tid] = s;
    }
    __syncthreads();

    // Last block per nc reduces + normalizes.
    if (tid == 0) {
        __threadfence();
        unsigned old = atomicAdd(&g_cnt[nc], 1u);
        slast = (old == SPLITS - 1);
    }
    __syncthreads();
    if (!slast) return;
    __threadfence();

    float bsum = 0.0f;
    if (tid < HB) {
        const float* p = g_part + (size_t)nc * SPLITS * HB + tid;
#pragma unroll
        for (int sp = 0; sp < SPLITS; ++sp)
            bsum += p[(size_t)sp * HB];
    }
    float v = (tid < HB) ? bsum : 0.0f;
    float r = v;
#pragma unroll
    for (int o = 16; o; o >>= 1) r += __shfl_xor_sync(0xffffffffu, r, o);
    if (tid == 0)  ws[0] = r;
    if (tid == 32) ws[1] = r;
    __syncthreads();
    float tot = ws[0] + ws[1];

    if (tid < HB)
        out[nc * HB + tid] = v / (tot + 1e-8f);

    if (tid == 0) g_cnt[nc] = 0;   // reset for next graph replay
}

extern "C" void kernel_launch(void* const* d_in, const int* in_sizes, int n_in,
                              void* d_out, int out_size) {
    const float* x        = (const float*)d_in[0];
    const float* bin_vals = (const float*)d_in[1];
    float* out            = (float*)d_out;

    dim3 grid(SPLITS, NC_TOTAL);
    hist_fused_kernel<<<grid, NT>>>(x, bin_vals, out);
}